// round 6
// baseline (speedup 1.0000x reference)
#include <cuda_runtime.h>
#include <cuda_bf16.h>

// PyramidROIAlign, flat task-space formulation.
// Task = one float4 of output. total_tasks = N*49*64.
// Block of 256 threads owns 1024 CONTIGUOUS tasks -> output stores are a pure
// linear stream (out + 4*g). The block's 1024 tasks span exactly 16 (roi,pos)
// metadata entries; threads 0..15 recompute those into smem (redundant but
// trivial). Each thread then processes 4 tasks (stride 256) with all 16 corner
// loads issued before any compute.

#define NPOS   49
#define C      256
#define CQ     64                 // float4 groups per (roi,pos)
#define TASKS_PER_BLOCK 1024
#define PP_PER_BLOCK    16        // 1024 / 64

struct PPMeta {
    int   o00, o01, o10, o11;     // float offsets into the level map
    float wx, wy;
    const float* base;            // level map base pointer
};

__global__ __launch_bounds__(256) void pyramid_roi_align_kernel(
    const float* __restrict__ boxes,   // [N,4]
    const float* __restrict__ meta,    // [93]
    const float* __restrict__ P2,      // [256,256,256]
    const float* __restrict__ P3,      // [128,128,256]
    const float* __restrict__ P4,      // [64,64,256]
    const float* __restrict__ P5,      // [32,32,256]
    float* __restrict__ out,           // [N,49,256]
    int num_pp,                        // N*49
    int num_tasks)                     // N*49*64
{
    const int tid = threadIdx.x;
    __shared__ PPMeta s_pp[PP_PER_BLOCK];

    // ---- per-block metadata: 16 (roi,pos) entries
    if (tid < PP_PER_BLOCK) {
        const int pp = blockIdx.x * PP_PER_BLOCK + tid;
        if (pp < num_pp) {
            const int roi = pp / NPOS;
            const int pos = pp - roi * NPOS;

            const float y1 = boxes[roi * 4 + 0];
            const float x1 = boxes[roi * 4 + 1];
            const float y2 = boxes[roi * 4 + 2];
            const float x2 = boxes[roi * 4 + 3];
            const float h = y2 - y1;
            const float w = x2 - x1;

            const float img_h = meta[4];
            const float img_w = meta[5];
            const float scale = 224.0f / sqrtf(img_h * img_w);
            const float lvl_f = log2f(sqrtf(h * w) / scale);
            int level = 4 + (int)rintf(lvl_f);       // round-half-even == jnp.round
            level = min(max(level, 2), 5);

            const int H = 1024 >> level;             // 256,128,64,32
            const int W = H;

            const int py = pos / 7;
            const int px = pos - py * 7;
            const float ys = (y1 + (float)py * (1.0f / 6.0f) * h) * (float)(H - 1);
            const float xs = (x1 + (float)px * (1.0f / 6.0f) * w) * (float)(W - 1);

            const float y0f = fminf(fmaxf(floorf(ys), 0.0f), (float)(H - 1));
            const float x0f = fminf(fmaxf(floorf(xs), 0.0f), (float)(W - 1));
            const int y0  = (int)y0f;
            const int x0  = (int)x0f;
            const int y1i = min(y0 + 1, H - 1);
            const int x1i = min(x0 + 1, W - 1);

            PPMeta m;
            m.wy  = ys - y0f;
            m.wx  = xs - x0f;
            m.o00 = (y0  * W + x0 ) * C;
            m.o01 = (y0  * W + x1i) * C;
            m.o10 = (y1i * W + x0 ) * C;
            m.o11 = (y1i * W + x1i) * C;
            m.base = (level == 2) ? P2 : (level == 3) ? P3 : (level == 4) ? P4 : P5;
            s_pp[tid] = m;
        }
    }
    __syncthreads();

    const int g0 = blockIdx.x * TASKS_PER_BLOCK + tid;   // thread's first task
    const int cg = (tid & 63) << 2;                      // channel offset (floats), same for all 4 tasks

    // ---- gather metadata + addresses for 4 tasks
    const float* addr[4][4];
    float wxv[4], wyv[4];
    bool  ok[4];

    #pragma unroll
    for (int k = 0; k < 4; k++) {
        const int g = g0 + k * 256;
        ok[k] = (g < num_tasks);
        const int lpp = (tid >> 6) + k * 4;              // local pp entry, 0..15
        const PPMeta m = s_pp[ok[k] ? lpp : 0];
        wxv[k] = m.wx;
        wyv[k] = m.wy;
        const float* b = m.base;
        addr[k][0] = b + m.o00 + cg;
        addr[k][1] = b + m.o01 + cg;
        addr[k][2] = b + m.o10 + cg;
        addr[k][3] = b + m.o11 + cg;
    }

    // ---- issue all 16 loads, then compute, then store (batched for MLP)
    float4 v[4][4];
    #pragma unroll
    for (int k = 0; k < 4; k++) {
        if (ok[k]) {
            v[k][0] = __ldg((const float4*)addr[k][0]);
            v[k][1] = __ldg((const float4*)addr[k][1]);
            v[k][2] = __ldg((const float4*)addr[k][2]);
            v[k][3] = __ldg((const float4*)addr[k][3]);
        }
    }

    #pragma unroll
    for (int k = 0; k < 4; k++) {
        if (ok[k]) {
            const float wx = wxv[k], wy = wyv[k];
            const float4 v00 = v[k][0], v01 = v[k][1], v10 = v[k][2], v11 = v[k][3];
            float4 r;
            float t, bq;
            t = v00.x + (v01.x - v00.x) * wx;  bq = v10.x + (v11.x - v10.x) * wx;  r.x = t + (bq - t) * wy;
            t = v00.y + (v01.y - v00.y) * wx;  bq = v10.y + (v11.y - v10.y) * wx;  r.y = t + (bq - t) * wy;
            t = v00.z + (v01.z - v00.z) * wx;  bq = v10.z + (v11.z - v10.z) * wx;  r.z = t + (bq - t) * wy;
            t = v00.w + (v01.w - v00.w) * wx;  bq = v10.w + (v11.w - v10.w) * wx;  r.w = t + (bq - t) * wy;
            __stcs((float4*)(out + (long long)(g0 + k * 256) * 4), r);
        }
    }
}

extern "C" void kernel_launch(void* const* d_in, const int* in_sizes, int n_in,
                              void* d_out, int out_size) {
    const float* boxes = (const float*)d_in[0];   // ROIboxes [1,N,4]
    const float* meta  = (const float*)d_in[1];   // image_meta [1,93]
    const float* P2    = (const float*)d_in[2];
    const float* P3    = (const float*)d_in[3];
    const float* P4    = (const float*)d_in[4];
    const float* P5    = (const float*)d_in[5];
    float* out = (float*)d_out;

    const int N = in_sizes[0] / 4;
    const int num_pp = N * NPOS;
    const int num_tasks = num_pp * CQ;
    const int blocks = (num_tasks + TASKS_PER_BLOCK - 1) / TASKS_PER_BLOCK;
    pyramid_roi_align_kernel<<<blocks, 256>>>(boxes, meta, P2, P3, P4, P5, out,
                                              num_pp, num_tasks);
}